// round 1
// baseline (speedup 1.0000x reference)
#include <cuda_runtime.h>
#include <cstdint>
#include <cstddef>
#include <math.h>

// Problem constants
constexpr int Cc = 4;     // gate-groups (phi, omega, r, mu)
constexpr int Gg = 2;     // j/k gates
constexpr int Bb = 32;    // batch
constexpr int Uu = 256;   // units
constexpr int Tt = 200;   // subsampled timesteps
constexpr int OSC = 10;

// Scratch (static device globals — no allocation allowed)
__device__ float g_XP[(size_t)Cc * Tt * Gg * Bb * Uu];  // [c][t][g][b][v]  52.4 MB
__device__ float g_HS[(size_t)Cc * Tt * Bb * Uu];       // [c][t][b][u]    26.2 MB

// ---------------- packed fp32x2 helpers ----------------
__device__ __forceinline__ void ffma2(unsigned long long& acc,
                                      unsigned long long a,
                                      unsigned long long b) {
    asm("fma.rn.f32x2 %0, %1, %2, %0;" : "+l"(acc) : "l"(a), "l"(b));
}
__device__ __forceinline__ unsigned long long pack2(float w) {
    unsigned long long r;
    unsigned int u = __float_as_uint(w);
    asm("mov.b64 %0, {%1, %1};" : "=l"(r) : "r"(u));
    return r;
}
__device__ __forceinline__ float2 unpack2(unsigned long long a) {
    float2 f;
    asm("mov.b64 {%0, %1}, %2;" : "=f"(f.x), "=f"(f.y) : "l"(a));
    return f;
}

// ============================================================
// Kernel 1: xp[c][t][g][b][v] = sum_d x[b][10t][d] * Wx[c][g][d][v] + bx[c][g][v]
// Tiled SIMT fp32 GEMM with FFMA2. Tile: 64 (m=(b,t)) x 128 (v). K=256.
// grid: (vtile=2, mtile=100, cg=8), 256 threads.
// ============================================================
__global__ __launch_bounds__(256) void xp_gemm_kernel(
    const float* __restrict__ x,
    const float* __restrict__ Wx,
    const float* __restrict__ bx)
{
    __shared__ __align__(16) float As[16][68];   // [k][m], padded pitch (272B, 16B-mult)
    __shared__ __align__(16) float Bs[16][128];  // [k][n]

    const int tid = threadIdx.x;
    const int vt = blockIdx.x, mt = blockIdx.y, cg = blockIdx.z;
    const int c = cg >> 1, g = cg & 1;
    const int v0 = vt * 128;
    const int m0 = mt * 64;

    // A-tile loader mapping: 64 m-rows x 16 k; thread loads one float4
    const int a_m  = tid >> 2;   // 0..63
    const int a_kq = tid & 3;    // 0..3  (k = a_kq*4 .. +3)
    const int arow = m0 + a_m;
    const int ab = arow / 200, at = arow % 200;
    const float* aptr = x + ((size_t)ab * 2000 + (size_t)at * 10) * 256 + a_kq * 4;

    // B-tile loader mapping: 16 k x 128 n; thread loads two float4
    const int b_k = tid >> 4;    // 0..15
    const int b_n = tid & 15;    // 0..15
    const float* bptr = Wx + ((size_t)cg * 256 + b_k) * 256 + v0 + b_n * 8;

    // Compute mapping: thread tile = 4 m x 8 v
    const int tm = tid >> 4, tn = tid & 15;

    unsigned long long acc[4][4];
#pragma unroll
    for (int i = 0; i < 4; i++)
#pragma unroll
        for (int j = 0; j < 4; j++) acc[i][j] = 0ULL;

    // prefetch chunk 0
    float4 pA  = *(const float4*)(aptr);
    float4 pB0 = *(const float4*)(bptr);
    float4 pB1 = *(const float4*)(bptr + 4);

    for (int kc = 0; kc < 16; kc++) {
        __syncthreads();
        As[a_kq * 4 + 0][a_m] = pA.x;
        As[a_kq * 4 + 1][a_m] = pA.y;
        As[a_kq * 4 + 2][a_m] = pA.z;
        As[a_kq * 4 + 3][a_m] = pA.w;
        *(float4*)&Bs[b_k][b_n * 8]     = pB0;
        *(float4*)&Bs[b_k][b_n * 8 + 4] = pB1;
        __syncthreads();
        if (kc < 15) {
            const int k0 = (kc + 1) * 16;
            pA  = *(const float4*)(aptr + k0);
            pB0 = *(const float4*)(bptr + (size_t)k0 * 256);
            pB1 = *(const float4*)(bptr + (size_t)k0 * 256 + 4);
        }
#pragma unroll
        for (int k = 0; k < 16; k++) {
            float4 av = *(const float4*)&As[k][tm * 4];
            unsigned long long ap0 = pack2(av.x);
            unsigned long long ap1 = pack2(av.y);
            unsigned long long ap2 = pack2(av.z);
            unsigned long long ap3 = pack2(av.w);
            ulonglong2 bb0 = *(const ulonglong2*)&Bs[k][tn * 8];
            ulonglong2 bb1 = *(const ulonglong2*)&Bs[k][tn * 8 + 4];
            ffma2(acc[0][0], ap0, bb0.x); ffma2(acc[0][1], ap0, bb0.y);
            ffma2(acc[0][2], ap0, bb1.x); ffma2(acc[0][3], ap0, bb1.y);
            ffma2(acc[1][0], ap1, bb0.x); ffma2(acc[1][1], ap1, bb0.y);
            ffma2(acc[1][2], ap1, bb1.x); ffma2(acc[1][3], ap1, bb1.y);
            ffma2(acc[2][0], ap2, bb0.x); ffma2(acc[2][1], ap2, bb0.y);
            ffma2(acc[2][2], ap2, bb1.x); ffma2(acc[2][3], ap2, bb1.y);
            ffma2(acc[3][0], ap3, bb0.x); ffma2(acc[3][1], ap3, bb0.y);
            ffma2(acc[3][2], ap3, bb1.x); ffma2(acc[3][3], ap3, bb1.y);
        }
    }

    // Epilogue: add bias, store to g_XP[c][t][g][b][v]
    float4 bxa = *(const float4*)(bx + cg * 256 + v0 + tn * 8);
    float4 bxb = *(const float4*)(bx + cg * 256 + v0 + tn * 8 + 4);
#pragma unroll
    for (int i = 0; i < 4; i++) {
        const int m = m0 + tm * 4 + i;
        const int bq = m / 200, tq = m % 200;
        float* dst = g_XP + ((((size_t)(c * 200 + tq) * 2 + g) * 32 + bq) * 256) + v0 + tn * 8;
        float2 p0 = unpack2(acc[i][0]);
        float2 p1 = unpack2(acc[i][1]);
        float2 p2 = unpack2(acc[i][2]);
        float2 p3 = unpack2(acc[i][3]);
        float4 o0 = make_float4(p0.x + bxa.x, p0.y + bxa.y, p1.x + bxa.z, p1.y + bxa.w);
        float4 o1 = make_float4(p2.x + bxb.x, p2.y + bxb.y, p3.x + bxb.z, p3.y + bxb.w);
        *(float4*)dst       = o0;
        *(float4*)(dst + 4) = o1;
    }
}

// ============================================================
// Kernel 2: the 200-step recurrence.
// Cluster of 4 CTAs splits the 256 units into 4 slices of 64.
// CTA = (c, batch-group of 4, v-slice of 64). 128 CTAs = 1 wave.
// W_h slice (2 gates x 256u x 64v, 128 KB) resident in smem.
// Per step: each thread (uh,g,v) computes a half-K partial dot for
// 4 batches (packed f32x2 pairs), partials reduced through smem,
// gates applied, new h broadcast to all 4 cluster CTAs via DSMEM,
// cluster barrier, repeat.
// ============================================================
constexpr int REC_SMEM_FLOATS = 32768 /*Wsh*/ + 2048 /*hb x2*/ + 1024 /*part*/ + 128 /*bhs*/;
constexpr int REC_SMEM_BYTES = REC_SMEM_FLOATS * 4;  // 143,872 B

__global__ __launch_bounds__(256, 1) __cluster_dims__(4, 1, 1)
void rec_kernel(const float* __restrict__ Wh, const float* __restrict__ bh)
{
    extern __shared__ float sm[];
    float* Wsh  = sm;            // [g][u][v]  2*256*64
    float* hb   = sm + 32768;    // [buf][u][b] 2*256*4
    float* part = sm + 34816;    // [uh][g][v][b] 2*2*64*4
    float* bhs  = sm + 35840;    // [g][v] 2*64

    const int tid = threadIdx.x;
    const int vq = blockIdx.x;   // cluster rank / v-slice
    const int bg = blockIdx.y;
    const int c  = blockIdx.z;
    const int v0 = vq * 64;

    // --- load W_h slice (32768 floats, float4-vectorized) ---
    for (int i = tid; i < 2 * 256 * 16; i += 256) {
        const int g = i >> 12;
        const int rem = i & 4095;
        const int u = rem >> 4;
        const int q = rem & 15;
        float4 wv = *(const float4*)(Wh + (((size_t)(c * 2 + g) * 256 + u) * 256) + v0 + q * 4);
        *(float4*)(Wsh + g * 16384 + u * 64 + q * 4) = wv;
    }
    if (tid < 128) {
        const int g = tid >> 6, v = tid & 63;
        bhs[g * 64 + v] = bh[(c * 2 + g) * 256 + v0 + v];
    }
    for (int i = tid; i < 1024; i += 256) hb[i] = 0.0f;  // h0 = 0 (buffer 0)
    __syncthreads();
    asm volatile("barrier.cluster.arrive.aligned;" ::: "memory");
    asm volatile("barrier.cluster.wait.aligned;" ::: "memory");

    // dot-product role: (uh, g, v)
    const int uh = tid >> 7;
    const int gg = (tid >> 6) & 1;
    const int v  = tid & 63;
    // finalize role: (fb, fv)
    const int fb = tid >> 6;     // 0..3
    const int fv = tid & 63;
    const int tb = bg * 4 + fb;  // global batch index

    uint32_t hb_u32;
    asm("{ .reg .u64 t0; cvta.to.shared.u64 t0, %1; cvt.u32.u64 %0, t0; }"
        : "=r"(hb_u32) : "l"(hb));

    const float* wbase = Wsh + gg * 16384 + uh * (128 * 64) + v;

    for (int t = 0; t < Tt; t++) {
        const int buf = t & 1, nbuf = buf ^ 1;

        // prefetch this step's xp (consumed ~1000 cycles later)
        const float* xpp = g_XP + (((size_t)(c * 200 + t) * 2) * 32 + tb) * 256 + v0 + fv;
        const float xpj = __ldg(xpp);
        const float xpk = __ldg(xpp + 32 * 256);

        // partial dot over 128 u's, 4 batches packed as 2 f32x2 lanes
        const ulonglong2* hp2 = (const ulonglong2*)(hb + buf * 1024) + uh * 128;
        unsigned long long aA0 = 0, aA1 = 0, aB0 = 0, aB1 = 0;
#pragma unroll 4
        for (int i = 0; i < 128; i += 2) {
            ulonglong2 h0 = hp2[i];
            unsigned long long w0 = pack2(wbase[i * 64]);
            ffma2(aA0, h0.x, w0);
            ffma2(aB0, h0.y, w0);
            ulonglong2 h1 = hp2[i + 1];
            unsigned long long w1 = pack2(wbase[(i + 1) * 64]);
            ffma2(aA1, h1.x, w1);
            ffma2(aB1, h1.y, w1);
        }
        float2 s01a = unpack2(aA0), s01b = unpack2(aA1);
        float2 s23a = unpack2(aB0), s23b = unpack2(aB1);
        float4 ps = make_float4(s01a.x + s01b.x, s01a.y + s01b.y,
                                s23a.x + s23b.x, s23a.y + s23b.y);
        *(float4*)(part + ((uh * 2 + gg) * 64 + v) * 4) = ps;
        __syncthreads();

        // finalize: combine partials, gates, h update
        const float pj = part[fv * 4 + fb] + part[(128 + fv) * 4 + fb] + bhs[fv];
        const float pk = part[(64 + fv) * 4 + fb] + part[(192 + fv) * 4 + fb] + bhs[64 + fv];
        const float sj = 1.0f / (1.0f + expf(-(xpj + pj)));
        const float sk = 1.0f / (1.0f + expf(-(xpk + pk)));
        const float hold = hb[buf * 1024 + (v0 + fv) * 4 + fb];
        const float hnew = sj * (1.0f - hold) + (1.0f - sk) * hold;

        // store to global for the oscillator pass
        g_HS[((size_t)(c * 200 + t) * 32 + tb) * 256 + v0 + fv] = hnew;

        // broadcast new-h slice to all 4 cluster CTAs' next-buffer
        const uint32_t laddr = hb_u32 + (uint32_t)(nbuf * 1024 + (v0 + fv) * 4 + fb) * 4u;
#pragma unroll
        for (int r = 0; r < 4; r++) {
            uint32_t ra;
            asm("mapa.shared::cluster.u32 %0, %1, %2;" : "=r"(ra) : "r"(laddr), "r"(r));
            asm volatile("st.shared::cluster.f32 [%0], %1;" :: "r"(ra), "f"(hnew));
        }
        asm volatile("barrier.cluster.arrive.aligned;" ::: "memory");
        asm volatile("barrier.cluster.wait.aligned;" ::: "memory");
    }
}

// ============================================================
// Kernel 3: oscillator roll-out + output write.
// grid (t=200, b=32), 256 threads (u). Fully coalesced; DRAM-bound.
// ============================================================
__global__ __launch_bounds__(256) void osc_kernel(float* __restrict__ out)
{
    const int t = blockIdx.x, b = blockIdx.y, u = threadIdx.x;
    const size_t base = ((size_t)t * 32 + b) * 256 + u;
    constexpr size_t CS = (size_t)200 * 32 * 256;
    float phi   = g_HS[0 * CS + base];
    float omega = g_HS[1 * CS + base];
    float r     = g_HS[2 * CS + base];
    float mu    = g_HS[3 * CS + base];
    float* o = out + ((size_t)b * 2000 + (size_t)t * 10) * 256 + u;
#pragma unroll
    for (int s = 0; s < OSC; s++) {
        o[(size_t)s * 256] = r * cosf(phi);
        r = r + (mu - r * r) * r;
        phi = phi + omega;
    }
}

// ============================================================
extern "C" void kernel_launch(void* const* d_in, const int* in_sizes, int n_in,
                              void* d_out, int out_size)
{
    const float* x  = (const float*)d_in[0];  // (32, 2000, 256)
    const float* Wx = (const float*)d_in[1];  // (4, 2, 256, 256)
    const float* bx = (const float*)d_in[2];  // (4, 2, 256)
    const float* Wh = (const float*)d_in[3];  // (4, 2, 256, 256)
    const float* bh = (const float*)d_in[4];  // (4, 2, 256)
    float* out = (float*)d_out;               // (32, 2000, 256)

    cudaFuncSetAttribute(rec_kernel, cudaFuncAttributeMaxDynamicSharedMemorySize,
                         REC_SMEM_BYTES);

    xp_gemm_kernel<<<dim3(2, 100, 8), 256>>>(x, Wx, bx);
    rec_kernel<<<dim3(4, 8, 4), 256, REC_SMEM_BYTES>>>(Wh, bh);
    osc_kernel<<<dim3(200, 32), 256>>>(out);
}

// round 3
// speedup vs baseline: 1.3511x; 1.3511x over previous
#include <cuda_runtime.h>
#include <cstdint>
#include <cstddef>
#include <math.h>

// Problem constants
constexpr int Cc = 4;     // gate-groups (phi, omega, r, mu)
constexpr int Bb = 32;    // batch
constexpr int Uu = 256;   // units
constexpr int Tt = 200;   // subsampled timesteps
constexpr int OSC = 10;

// Scratch (static device globals — no allocation allowed)
__device__ float g_XP[(size_t)Cc * Tt * 2 * Bb * Uu];  // [c][t][g][b][v]  52.4 MB
__device__ float g_HS[(size_t)Cc * Tt * Bb * Uu];      // [c][t][b][u]    26.2 MB

// ---------------- packed fp32x2 helpers ----------------
__device__ __forceinline__ void ffma2(unsigned long long& acc,
                                      unsigned long long a,
                                      unsigned long long b) {
    asm("fma.rn.f32x2 %0, %1, %2, %0;" : "+l"(acc) : "l"(a), "l"(b));
}
__device__ __forceinline__ unsigned long long pack2(float w) {
    unsigned long long r;
    unsigned int u = __float_as_uint(w);
    asm("mov.b64 %0, {%1, %1};" : "=l"(r) : "r"(u));
    return r;
}
__device__ __forceinline__ unsigned long long packab(float a, float b) {
    unsigned long long r;
    asm("mov.b64 %0, {%1, %2};" : "=l"(r) : "f"(a), "f"(b));
    return r;
}
__device__ __forceinline__ float2 unpack2(unsigned long long a) {
    float2 f;
    asm("mov.b64 {%0, %1}, %2;" : "=f"(f.x), "=f"(f.y) : "l"(a));
    return f;
}
__device__ __forceinline__ uint32_t smem_u32(const void* p) {
    uint32_t a;
    asm("{ .reg .u64 t0; cvta.to.shared.u64 t0, %1; cvt.u32.u64 %0, t0; }"
        : "=r"(a) : "l"(p));
    return a;
}
__device__ __forceinline__ float sigmoidf_fast(float x) {
    return __fdividef(1.0f, 1.0f + __expf(-x));
}
__device__ __forceinline__ void mbar_wait_parity(uint32_t mbar, uint32_t parity) {
    uint32_t done;
    asm volatile(
        "{\n\t.reg .pred p;\n\t"
        "mbarrier.try_wait.parity.acquire.cluster.shared::cta.b64 p, [%1], %2;\n\t"
        "selp.b32 %0, 1, 0, p;\n\t}"
        : "=r"(done) : "r"(mbar), "r"(parity) : "memory");
    if (!done) {
        asm volatile(
            "{\n\t.reg .pred P1;\n\t"
            "WL_%=:\n\t"
            "mbarrier.try_wait.parity.acquire.cluster.shared::cta.b64 P1, [%0], %1, 0x989680;\n\t"
            "@P1 bra.uni WD_%=;\n\t"
            "bra.uni WL_%=;\n\t"
            "WD_%=:\n\t}"
            :: "r"(mbar), "r"(parity) : "memory");
    }
}

// ============================================================
// Kernel 1 (v2): xp GEMM, 128x128 CTA tile, 8m x 8v per thread.
// grid (vt=2, mt=50, cg=8) = 800 CTAs, 256 threads.
// A-tile reads are 2-address broadcasts; bytes/MAC = 1.0.
// ============================================================
__global__ __launch_bounds__(256) void xp_gemm_kernel(
    const float* __restrict__ x,
    const float* __restrict__ Wx,
    const float* __restrict__ bx)
{
    __shared__ __align__(16) float As[16][132];  // [k][m], pitch 132
    __shared__ __align__(16) float Bs[16][128];  // [k][n]

    const int tid = threadIdx.x;
    const int vt = blockIdx.x, mt = blockIdx.y, cg = blockIdx.z;
    const int c = cg >> 1, g = cg & 1;
    const int v0 = vt * 128;
    const int m0 = mt * 128;

    // A loader: threads 0-127 load k=0..7, 128-255 load k=8..15; a_m = tid&127.
    const int a_m  = tid & 127;
    const int a_kh = tid >> 7;   // k half (0/1)
    const int arow = m0 + a_m;
    const int ab = arow / 200, at = arow % 200;
    const float* aptr = x + ((size_t)ab * 2000 + (size_t)at * 10) * 256 + a_kh * 8;

    // B loader: (b_k = tid>>4 in 0..15, b_n = tid&15), 2 float4 each
    const int b_k = tid >> 4;
    const int b_n = tid & 15;
    const float* bptr = Wx + ((size_t)cg * 256 + b_k) * 256 + v0 + b_n * 8;

    // Compute mapping: thread tile = 8 m x 8 v
    const int tm = tid >> 4, tn = tid & 15;

    unsigned long long acc[8][4];
#pragma unroll
    for (int i = 0; i < 8; i++)
#pragma unroll
        for (int j = 0; j < 4; j++) acc[i][j] = 0ULL;

    float4 pA0 = *(const float4*)(aptr);
    float4 pA1 = *(const float4*)(aptr + 4);
    float4 pB0 = *(const float4*)(bptr);
    float4 pB1 = *(const float4*)(bptr + 4);

    for (int kc = 0; kc < 16; kc++) {
        __syncthreads();
        {
            const int kb = a_kh * 8;
            As[kb + 0][a_m] = pA0.x;
            As[kb + 1][a_m] = pA0.y;
            As[kb + 2][a_m] = pA0.z;
            As[kb + 3][a_m] = pA0.w;
            As[kb + 4][a_m] = pA1.x;
            As[kb + 5][a_m] = pA1.y;
            As[kb + 6][a_m] = pA1.z;
            As[kb + 7][a_m] = pA1.w;
        }
        *(float4*)&Bs[b_k][b_n * 8]     = pB0;
        *(float4*)&Bs[b_k][b_n * 8 + 4] = pB1;
        __syncthreads();
        if (kc < 15) {
            const int k0 = (kc + 1) * 16;
            pA0 = *(const float4*)(aptr + k0);
            pA1 = *(const float4*)(aptr + k0 + 4);
            pB0 = *(const float4*)(bptr + (size_t)k0 * 256);
            pB1 = *(const float4*)(bptr + (size_t)k0 * 256 + 4);
        }
#pragma unroll
        for (int k = 0; k < 16; k++) {
            float4 a0 = *(const float4*)&As[k][tm * 8];
            float4 a1 = *(const float4*)&As[k][tm * 8 + 4];
            ulonglong2 bb0 = *(const ulonglong2*)&Bs[k][tn * 8];
            ulonglong2 bb1 = *(const ulonglong2*)&Bs[k][tn * 8 + 4];
            unsigned long long ap0 = pack2(a0.x);
            unsigned long long ap1 = pack2(a0.y);
            unsigned long long ap2 = pack2(a0.z);
            unsigned long long ap3 = pack2(a0.w);
            unsigned long long ap4 = pack2(a1.x);
            unsigned long long ap5 = pack2(a1.y);
            unsigned long long ap6 = pack2(a1.z);
            unsigned long long ap7 = pack2(a1.w);
            ffma2(acc[0][0], ap0, bb0.x); ffma2(acc[0][1], ap0, bb0.y);
            ffma2(acc[0][2], ap0, bb1.x); ffma2(acc[0][3], ap0, bb1.y);
            ffma2(acc[1][0], ap1, bb0.x); ffma2(acc[1][1], ap1, bb0.y);
            ffma2(acc[1][2], ap1, bb1.x); ffma2(acc[1][3], ap1, bb1.y);
            ffma2(acc[2][0], ap2, bb0.x); ffma2(acc[2][1], ap2, bb0.y);
            ffma2(acc[2][2], ap2, bb1.x); ffma2(acc[2][3], ap2, bb1.y);
            ffma2(acc[3][0], ap3, bb0.x); ffma2(acc[3][1], ap3, bb0.y);
            ffma2(acc[3][2], ap3, bb1.x); ffma2(acc[3][3], ap3, bb1.y);
            ffma2(acc[4][0], ap4, bb0.x); ffma2(acc[4][1], ap4, bb0.y);
            ffma2(acc[4][2], ap4, bb1.x); ffma2(acc[4][3], ap4, bb1.y);
            ffma2(acc[5][0], ap5, bb0.x); ffma2(acc[5][1], ap5, bb0.y);
            ffma2(acc[5][2], ap5, bb1.x); ffma2(acc[5][3], ap5, bb1.y);
            ffma2(acc[6][0], ap6, bb0.x); ffma2(acc[6][1], ap6, bb0.y);
            ffma2(acc[6][2], ap6, bb1.x); ffma2(acc[6][3], ap6, bb1.y);
            ffma2(acc[7][0], ap7, bb0.x); ffma2(acc[7][1], ap7, bb0.y);
            ffma2(acc[7][2], ap7, bb1.x); ffma2(acc[7][3], ap7, bb1.y);
        }
    }

    // Epilogue: add bias, store 8 rows x 8 cols
    float4 bxa = *(const float4*)(bx + cg * 256 + v0 + tn * 8);
    float4 bxb = *(const float4*)(bx + cg * 256 + v0 + tn * 8 + 4);
#pragma unroll
    for (int i = 0; i < 8; i++) {
        const int m = m0 + tm * 8 + i;
        const int bq = m / 200, tq = m % 200;
        float* dst = g_XP + ((((size_t)(c * 200 + tq) * 2 + g) * 32 + bq) * 256) + v0 + tn * 8;
        float2 p0 = unpack2(acc[i][0]);
        float2 p1 = unpack2(acc[i][1]);
        float2 p2 = unpack2(acc[i][2]);
        float2 p3 = unpack2(acc[i][3]);
        float4 o0 = make_float4(p0.x + bxa.x, p0.y + bxa.y, p1.x + bxa.z, p1.y + bxa.w);
        float4 o1 = make_float4(p2.x + bxb.x, p2.y + bxb.y, p3.x + bxb.z, p3.y + bxb.w);
        *(float4*)dst       = o0;
        *(float4*)(dst + 4) = o1;
    }
}

// ============================================================
// Kernel 2: 200-step recurrence (R2 design, bg-index bug FIXED).
// ============================================================
constexpr int OFF_HB   = 32768;            // hb[2][256][4] floats
constexpr int OFF_PART = 32768 + 2048;     // 5120 pairs = 10240 floats
constexpr int OFF_BHS  = OFF_PART + 10240; // 128 floats
constexpr int OFF_MBAR = OFF_BHS + 128;    // 2 x u64 (4 floats)
constexpr int REC_SMEM_BYTES = (OFF_MBAR + 4) * 4;

__global__ __launch_bounds__(512, 1) __cluster_dims__(4, 1, 1)
void rec_kernel(const float* __restrict__ Wh, const float* __restrict__ bh)
{
    extern __shared__ float sm[];
    float* Wsh = sm;                                        // [g][u][64v]
    float* hb  = sm + OFF_HB;                               // [buf][u][b]
    unsigned long long* part = (unsigned long long*)(sm + OFF_PART);
    float* bhs = sm + OFF_BHS;                              // [g][v]

    const int tid = threadIdx.x;
    const int vq = blockIdx.x;   // cluster rank / v-slice
    const int bg = blockIdx.y;
    const int c  = blockIdx.z;
    const int v0 = vq * 64;

    const uint32_t mbar_u32 = smem_u32(sm + OFF_MBAR);
    const uint32_t hb_u32   = smem_u32(hb);

    // ---- init: W slice, biases, h0=0, mbarriers ----
    for (int i = tid; i < 2 * 256 * 16; i += 512) {
        const int g = i >> 12;
        const int rem = i & 4095;
        const int u = rem >> 4;
        const int q = rem & 15;
        float4 wv = *(const float4*)(Wh + (((size_t)(c * 2 + g) * 256 + u) * 256) + v0 + q * 4);
        *(float4*)(Wsh + g * 16384 + u * 64 + q * 4) = wv;
    }
    if (tid < 128) {
        const int g = tid >> 6, v = tid & 63;
        bhs[g * 64 + v] = bh[(c * 2 + g) * 256 + v0 + v];
    }
    for (int i = tid; i < 2048; i += 512) hb[i] = 0.0f;
    if (tid == 0) {
        asm volatile("mbarrier.init.shared.b64 [%0], %1;" :: "r"(mbar_u32), "r"(1) : "memory");
        asm volatile("mbarrier.init.shared.b64 [%0], %1;" :: "r"(mbar_u32 + 8), "r"(1) : "memory");
    }
    __syncthreads();
    asm volatile("barrier.cluster.arrive.aligned;" ::: "memory");
    asm volatile("barrier.cluster.wait.aligned;" ::: "memory");

    // dot roles
    const int wid  = tid >> 5;
    const int lane = tid & 31;
    const int vgrp = lane >> 2;
    const int b    = lane & 3;
    const float* w0p = Wsh + wid * 1024 + vgrp * 8;   // g=0, u base wid*16
    const float* w1p = w0p + 16384;                   // g=1
    unsigned long long* pp = part + ((size_t)wid * 2 * 32) * 5 + b;

    // finalize roles (tid < 128)
    const int fv  = tid & 63;
    const int fbp = (tid >> 6) & 1;   // batch pair
    const int vp  = fv >> 1, sel = fv & 1;

    uint32_t par[2] = {0u, 0u};

    for (int t = 0; t < Tt; t++) {
        const int buf = t & 1, nbuf = buf ^ 1;

        if (tid == 0 && t + 1 < Tt) {
            asm volatile("mbarrier.arrive.expect_tx.shared.b64 _, [%0], %1;"
                         :: "r"(mbar_u32 + nbuf * 8), "r"(4096) : "memory");
        }

        // prefetch xp for finalize (consumed after the dot)
        float xq00, xq01, xq10, xq11;
        if (tid < 128) {
            // g_XP[c][t][g][b][v]; global batch = bg*4 + fbp*2 (+1)
            const float* xpb = g_XP
                + (((size_t)(c * 200 + t) * 2 * 32) + bg * 4 + fbp * 2) * 256
                + v0 + fv;
            xq00 = __ldg(xpb);                       // g=0, b0
            xq01 = __ldg(xpb + 256);                 // g=0, b1
            xq10 = __ldg(xpb + 32 * 256);            // g=1, b0
            xq11 = __ldg(xpb + 33 * 256);            // g=1, b1
        }

        if (t > 0) {
            mbar_wait_parity(mbar_u32 + buf * 8, par[buf]);
            par[buf] ^= 1u;
        }

        // ---- dot: 16 u's, both gates, 4 v-pairs, one batch ----
        unsigned long long a00 = 0, a01 = 0, a02 = 0, a03 = 0;
        unsigned long long a10 = 0, a11 = 0, a12 = 0, a13 = 0;
        const float* hB = hb + buf * 1024 + wid * 64 + b;
#pragma unroll
        for (int i = 0; i < 16; i++) {
            unsigned long long m = pack2(hB[i * 4]);
            ulonglong2 wA = *(const ulonglong2*)(w0p + i * 64);
            ulonglong2 wB = *(const ulonglong2*)(w0p + i * 64 + 4);
            ulonglong2 wC = *(const ulonglong2*)(w1p + i * 64);
            ulonglong2 wD = *(const ulonglong2*)(w1p + i * 64 + 4);
            ffma2(a00, m, wA.x); ffma2(a01, m, wA.y);
            ffma2(a02, m, wB.x); ffma2(a03, m, wB.y);
            ffma2(a10, m, wC.x); ffma2(a11, m, wC.y);
            ffma2(a12, m, wD.x); ffma2(a13, m, wD.y);
        }
        // store partials: [wid][g][vp][b(pad5)]
        {
            unsigned long long* q0 = pp + (size_t)(vgrp * 4) * 5;
            q0[0]  = a00; q0[5]  = a01; q0[10] = a02; q0[15] = a03;
            unsigned long long* q1 = q0 + (size_t)32 * 5;
            q1[0]  = a10; q1[5]  = a11; q1[10] = a12; q1[15] = a13;
        }
        __syncthreads();

        // ---- finalize ----
        if (tid < 128) {
            const float* pf = (const float*)part;
            const int i00 = (vp * 5 + fbp * 2) * 2 + sel;              // g=0
            const int i10 = ((32 + vp) * 5 + fbp * 2) * 2 + sel;       // g=1
            float s00 = 0.f, s01 = 0.f, s10 = 0.f, s11 = 0.f;
#pragma unroll
            for (int w = 0; w < 16; w++) {
                const float* q = pf + w * 640;
                s00 += q[i00];     s01 += q[i00 + 2];
                s10 += q[i10];     s11 += q[i10 + 2];
            }
            const float bj = bhs[fv], bk = bhs[64 + fv];
            const float j0 = sigmoidf_fast(xq00 + s00 + bj);
            const float j1 = sigmoidf_fast(xq01 + s01 + bj);
            const float k0 = sigmoidf_fast(xq10 + s10 + bk);
            const float k1 = sigmoidf_fast(xq11 + s11 + bk);
            const int hoff = buf * 1024 + (v0 + fv) * 4 + fbp * 2;
            const float h0 = hb[hoff], h1 = hb[hoff + 1];
            const float hn0 = j0 * (1.0f - h0) + (1.0f - k0) * h0;
            const float hn1 = j1 * (1.0f - h1) + (1.0f - k1) * h1;

            // g_HS[c][t][b][u]
            float* hs = g_HS + ((size_t)(c * 200 + t) * 32 + bg * 4 + fbp * 2) * 256 + v0 + fv;
            hs[0]   = hn0;
            hs[256] = hn1;

            if (t + 1 < Tt) {
                const unsigned long long val = packab(hn0, hn1);
                const uint32_t laddr = hb_u32 +
                    (uint32_t)(nbuf * 1024 + (v0 + fv) * 4 + fbp * 2) * 4u;
                const uint32_t lmbar = mbar_u32 + nbuf * 8;
#pragma unroll
                for (int r = 0; r < 4; r++) {
                    uint32_t ra, rm;
                    asm("mapa.shared::cluster.u32 %0, %1, %2;" : "=r"(ra) : "r"(laddr), "r"(r));
                    asm("mapa.shared::cluster.u32 %0, %1, %2;" : "=r"(rm) : "r"(lmbar), "r"(r));
                    asm volatile(
                        "st.async.shared::cluster.mbarrier::complete_tx::bytes.b64 [%0], %1, [%2];"
                        :: "r"(ra), "l"(val), "r"(rm) : "memory");
                }
            }
        }
        // No syncthreads: step t+1's dot can't pass its mbarrier wait until
        // every CTA's finalize (incl. ours) has stored.
    }

    asm volatile("barrier.cluster.arrive.aligned;" ::: "memory");
    asm volatile("barrier.cluster.wait.aligned;" ::: "memory");
}

// ============================================================
// Kernel 3: oscillator roll-out + output write.
// ============================================================
__global__ __launch_bounds__(256) void osc_kernel(float* __restrict__ out)
{
    const int t = blockIdx.x, b = blockIdx.y, u = threadIdx.x;
    const size_t base = ((size_t)t * 32 + b) * 256 + u;
    constexpr size_t CS = (size_t)200 * 32 * 256;
    float phi   = g_HS[0 * CS + base];
    float omega = g_HS[1 * CS + base];
    float r     = g_HS[2 * CS + base];
    float mu    = g_HS[3 * CS + base];
    float* o = out + ((size_t)b * 2000 + (size_t)t * 10) * 256 + u;
#pragma unroll
    for (int s = 0; s < OSC; s++) {
        o[(size_t)s * 256] = r * cosf(phi);
        r = r + (mu - r * r) * r;
        phi = phi + omega;
    }
}

// ============================================================
extern "C" void kernel_launch(void* const* d_in, const int* in_sizes, int n_in,
                              void* d_out, int out_size)
{
    const float* x  = (const float*)d_in[0];  // (32, 2000, 256)
    const float* Wx = (const float*)d_in[1];  // (4, 2, 256, 256)
    const float* bx = (const float*)d_in[2];  // (4, 2, 256)
    const float* Wh = (const float*)d_in[3];  // (4, 2, 256, 256)
    const float* bh = (const float*)d_in[4];  // (4, 2, 256)
    float* out = (float*)d_out;               // (32, 2000, 256)

    cudaFuncSetAttribute(rec_kernel, cudaFuncAttributeMaxDynamicSharedMemorySize,
                         REC_SMEM_BYTES);

    xp_gemm_kernel<<<dim3(2, 50, 8), 256>>>(x, Wx, bx);
    rec_kernel<<<dim3(4, 8, 4), 512, REC_SMEM_BYTES>>>(Wh, bh);
    osc_kernel<<<dim3(200, 32), 256>>>(out);
}

// round 4
// speedup vs baseline: 1.3912x; 1.0296x over previous
#include <cuda_runtime.h>
#include <cstdint>
#include <cstddef>
#include <math.h>

typedef unsigned long long ull;

// Problem constants
constexpr int Cc = 4;
constexpr int Bb = 32;
constexpr int Uu = 256;
constexpr int Tt = 200;
constexpr int OSC = 10;

// Scratch (static device globals — no allocation allowed)
__device__ float g_XP[(size_t)Cc * Tt * 2 * Bb * Uu];  // [c][t][g][b][v]
__device__ float g_HS[(size_t)Cc * Tt * Bb * Uu];      // [c][t][b][u]

// ---------------- packed fp32x2 helpers ----------------
__device__ __forceinline__ void ffma2(ull& acc, ull a, ull b) {
    asm("fma.rn.f32x2 %0, %1, %2, %0;" : "+l"(acc) : "l"(a), "l"(b));
}
__device__ __forceinline__ ull add2(ull a, ull b) {
    ull r;
    asm("add.rn.f32x2 %0, %1, %2;" : "=l"(r) : "l"(a), "l"(b));
    return r;
}
__device__ __forceinline__ ull pack2(float w) {
    ull r;
    unsigned int u = __float_as_uint(w);
    asm("mov.b64 %0, {%1, %1};" : "=l"(r) : "r"(u));
    return r;
}
__device__ __forceinline__ float2 unpack2(ull a) {
    float2 f;
    asm("mov.b64 {%0, %1}, %2;" : "=f"(f.x), "=f"(f.y) : "l"(a));
    return f;
}
__device__ __forceinline__ uint32_t smem_u32(const void* p) {
    uint32_t a;
    asm("{ .reg .u64 t0; cvta.to.shared.u64 t0, %1; cvt.u32.u64 %0, t0; }"
        : "=r"(a) : "l"(p));
    return a;
}
__device__ __forceinline__ float sigmoidf_fast(float x) {
    return __fdividef(1.0f, 1.0f + __expf(-x));
}
__device__ __forceinline__ void mbar_wait_parity(uint32_t mbar, uint32_t parity) {
    uint32_t done;
    asm volatile(
        "{\n\t.reg .pred p;\n\t"
        "mbarrier.try_wait.parity.acquire.cluster.shared::cta.b64 p, [%1], %2;\n\t"
        "selp.b32 %0, 1, 0, p;\n\t}"
        : "=r"(done) : "r"(mbar), "r"(parity) : "memory");
    if (!done) {
        asm volatile(
            "{\n\t.reg .pred P1;\n\t"
            "WL_%=:\n\t"
            "mbarrier.try_wait.parity.acquire.cluster.shared::cta.b64 P1, [%0], %1, 0x989680;\n\t"
            "@P1 bra.uni WD_%=;\n\t"
            "bra.uni WL_%=;\n\t"
            "WD_%=:\n\t}"
            :: "r"(mbar), "r"(parity) : "memory");
    }
}

// ============================================================
// Kernel 1 (v3): xp GEMM, 128x128 tile, 8m x 8v / thread,
// double-buffered smem, ONE __syncthreads per k-chunk.
// ============================================================
__global__ __launch_bounds__(256) void xp_gemm_kernel(
    const float* __restrict__ x,
    const float* __restrict__ Wx,
    const float* __restrict__ bx)
{
    __shared__ __align__(16) float As[2][16][132];
    __shared__ __align__(16) float Bs[2][16][128];

    const int tid = threadIdx.x;
    const int vt = blockIdx.x, mt = blockIdx.y, cg = blockIdx.z;
    const int c = cg >> 1, g = cg & 1;
    const int v0 = vt * 128;
    const int m0 = mt * 128;

    const int a_m  = tid & 127;
    const int a_kh = tid >> 7;
    const int arow = m0 + a_m;
    const int ab = arow / 200, at = arow % 200;
    const float* aptr = x + ((size_t)ab * 2000 + (size_t)at * 10) * 256 + a_kh * 8;

    const int b_k = tid >> 4;
    const int b_n = tid & 15;
    const float* bptr = Wx + ((size_t)cg * 256 + b_k) * 256 + v0 + b_n * 8;

    const int tm = tid >> 4, tn = tid & 15;

    ull acc[8][4];
#pragma unroll
    for (int i = 0; i < 8; i++)
#pragma unroll
        for (int j = 0; j < 4; j++) acc[i][j] = 0ULL;

    float4 pA0 = *(const float4*)(aptr);
    float4 pA1 = *(const float4*)(aptr + 4);
    float4 pB0 = *(const float4*)(bptr);
    float4 pB1 = *(const float4*)(bptr + 4);

    for (int kc = 0; kc < 16; kc++) {
        const int cur = kc & 1;
        {
            const int kb = a_kh * 8;
            As[cur][kb + 0][a_m] = pA0.x;
            As[cur][kb + 1][a_m] = pA0.y;
            As[cur][kb + 2][a_m] = pA0.z;
            As[cur][kb + 3][a_m] = pA0.w;
            As[cur][kb + 4][a_m] = pA1.x;
            As[cur][kb + 5][a_m] = pA1.y;
            As[cur][kb + 6][a_m] = pA1.z;
            As[cur][kb + 7][a_m] = pA1.w;
            *(float4*)&Bs[cur][b_k][b_n * 8]     = pB0;
            *(float4*)&Bs[cur][b_k][b_n * 8 + 4] = pB1;
        }
        __syncthreads();
        if (kc < 15) {
            const int k0 = (kc + 1) * 16;
            pA0 = *(const float4*)(aptr + k0);
            pA1 = *(const float4*)(aptr + k0 + 4);
            pB0 = *(const float4*)(bptr + (size_t)k0 * 256);
            pB1 = *(const float4*)(bptr + (size_t)k0 * 256 + 4);
        }
#pragma unroll
        for (int k = 0; k < 16; k++) {
            float4 a0 = *(const float4*)&As[cur][k][tm * 8];
            float4 a1 = *(const float4*)&As[cur][k][tm * 8 + 4];
            ulonglong2 bb0 = *(const ulonglong2*)&Bs[cur][k][tn * 8];
            ulonglong2 bb1 = *(const ulonglong2*)&Bs[cur][k][tn * 8 + 4];
            ull ap0 = pack2(a0.x), ap1 = pack2(a0.y);
            ull ap2 = pack2(a0.z), ap3 = pack2(a0.w);
            ull ap4 = pack2(a1.x), ap5 = pack2(a1.y);
            ull ap6 = pack2(a1.z), ap7 = pack2(a1.w);
            ffma2(acc[0][0], ap0, bb0.x); ffma2(acc[0][1], ap0, bb0.y);
            ffma2(acc[0][2], ap0, bb1.x); ffma2(acc[0][3], ap0, bb1.y);
            ffma2(acc[1][0], ap1, bb0.x); ffma2(acc[1][1], ap1, bb0.y);
            ffma2(acc[1][2], ap1, bb1.x); ffma2(acc[1][3], ap1, bb1.y);
            ffma2(acc[2][0], ap2, bb0.x); ffma2(acc[2][1], ap2, bb0.y);
            ffma2(acc[2][2], ap2, bb1.x); ffma2(acc[2][3], ap2, bb1.y);
            ffma2(acc[3][0], ap3, bb0.x); ffma2(acc[3][1], ap3, bb0.y);
            ffma2(acc[3][2], ap3, bb1.x); ffma2(acc[3][3], ap3, bb1.y);
            ffma2(acc[4][0], ap4, bb0.x); ffma2(acc[4][1], ap4, bb0.y);
            ffma2(acc[4][2], ap4, bb1.x); ffma2(acc[4][3], ap4, bb1.y);
            ffma2(acc[5][0], ap5, bb0.x); ffma2(acc[5][1], ap5, bb0.y);
            ffma2(acc[5][2], ap5, bb1.x); ffma2(acc[5][3], ap5, bb1.y);
            ffma2(acc[6][0], ap6, bb0.x); ffma2(acc[6][1], ap6, bb0.y);
            ffma2(acc[6][2], ap6, bb1.x); ffma2(acc[6][3], ap6, bb1.y);
            ffma2(acc[7][0], ap7, bb0.x); ffma2(acc[7][1], ap7, bb0.y);
            ffma2(acc[7][2], ap7, bb1.x); ffma2(acc[7][3], ap7, bb1.y);
        }
    }

    float4 bxa = *(const float4*)(bx + cg * 256 + v0 + tn * 8);
    float4 bxb = *(const float4*)(bx + cg * 256 + v0 + tn * 8 + 4);
#pragma unroll
    for (int i = 0; i < 8; i++) {
        const int m = m0 + tm * 8 + i;
        const int bq = m / 200, tq = m % 200;
        float* dst = g_XP + ((((size_t)(c * 200 + tq) * 2 + g) * 32 + bq) * 256) + v0 + tn * 8;
        float2 p0 = unpack2(acc[i][0]);
        float2 p1 = unpack2(acc[i][1]);
        float2 p2 = unpack2(acc[i][2]);
        float2 p3 = unpack2(acc[i][3]);
        float4 o0 = make_float4(p0.x + bxa.x, p0.y + bxa.y, p1.x + bxa.z, p1.y + bxa.w);
        float4 o1 = make_float4(p2.x + bxb.x, p2.y + bxb.y, p3.x + bxb.z, p3.y + bxb.w);
        *(float4*)dst       = o0;
        *(float4*)(dst + 4) = o1;
    }
}

// ============================================================
// Kernel 2 (v3): 200-step recurrence with REGISTER-RESIDENT W.
// Cluster of 4 CTAs splits 256 v into slices of 64.
// CTA = (vq, bg of 4 batches, c). 128 CTAs = 1 wave, 512 thr.
// Warp wid owns u-chunk [wid*16,+16); lane owns v-pair 2*lane.
// W in regs: Wr[g][i] = f32x2 (v-pair) — loaded once.
// Per step: dot = 16 broadcast LDS.128 of h + 128 FFMA2/thread;
// partial pairs through smem; finalize warps 0-3 apply gates
// (hold state in registers) and st.async h to all 4 cluster CTAs.
// ============================================================
constexpr int OFF_HB   = 0;      // hb[2][256][4] = 2048 floats
constexpr int OFF_PART = 2048;   // 4096 ull = 8192 floats
constexpr int OFF_BHS  = 10240;  // 128 floats
constexpr int OFF_MBAR = 10368;  // 2 ull
constexpr int REC_SMEM_BYTES = (10368 + 4) * 4;

__global__ __launch_bounds__(512, 1) __cluster_dims__(4, 1, 1)
void rec_kernel(const float* __restrict__ Wh, const float* __restrict__ bh)
{
    extern __shared__ float sm[];
    float* hb  = sm + OFF_HB;                     // [buf][u][b]
    ull*  part = (ull*)(sm + OFF_PART);           // [wid][g][b][vp]
    float* bhs = sm + OFF_BHS;                    // [g][64]

    const int tid = threadIdx.x;
    const int vq = blockIdx.x;
    const int bg = blockIdx.y;
    const int c  = blockIdx.z;
    const int v0 = vq * 64;

    const uint32_t mbar_u32 = smem_u32(sm + OFF_MBAR);
    const uint32_t hb_u32   = smem_u32(hb);

    const int wid  = tid >> 5;
    const int lane = tid & 31;

    // ---- load W slice into registers (once) ----
    ull Wr0[16], Wr1[16];
    {
        const float* wsrc = Wh + ((size_t)(c * 2) * 256 + wid * 16) * 256 + v0 + lane * 2;
#pragma unroll
        for (int i = 0; i < 16; i++) Wr0[i] = *(const ull*)(wsrc + i * 256);
#pragma unroll
        for (int i = 0; i < 16; i++) Wr1[i] = *(const ull*)(wsrc + 65536 + i * 256);
    }
    if (tid < 128) {
        const int g = tid >> 6, v = tid & 63;
        bhs[g * 64 + v] = bh[(c * 2 + g) * 256 + v0 + v];
    }
    for (int i = tid; i < 2048; i += 512) hb[i] = 0.0f;
    if (tid == 0) {
        asm volatile("mbarrier.init.shared.b64 [%0], %1;" :: "r"(mbar_u32), "r"(1) : "memory");
        asm volatile("mbarrier.init.shared.b64 [%0], %1;" :: "r"(mbar_u32 + 8), "r"(1) : "memory");
    }
    __syncthreads();
    asm volatile("barrier.cluster.arrive.aligned;" ::: "memory");
    asm volatile("barrier.cluster.wait.aligned;" ::: "memory");

    // finalize roles (tid < 128): fb = batch-in-group, vp = v-pair
    const int fb = tid >> 5;     // warp 0..3
    const int vp = tid & 31;
    const int B  = bg * 4 + fb;
    float hold0 = 0.0f, hold1 = 0.0f;
    const float* xpp = g_XP + (((size_t)(c * 200) * 2) * 32 + B) * 256 + v0 + 2 * vp;
    float* hsp = g_HS + ((size_t)(c * 200) * 32 + B) * 256 + v0 + 2 * vp;

    uint32_t par[2] = {0u, 0u};

    for (int t = 0; t < Tt; t++) {
        const int buf = t & 1, nbuf = buf ^ 1;

        if (tid == 0 && t + 1 < Tt) {
            asm volatile("mbarrier.arrive.expect_tx.shared.b64 _, [%0], %1;"
                         :: "r"(mbar_u32 + nbuf * 8), "r"(4096) : "memory");
        }

        // finalize-thread xp prefetch (consumed after dot)
        float2 xj, xk;
        if (tid < 128) {
            xj = *(const float2*)(xpp);
            xk = *(const float2*)(xpp + 32 * 256);
        }

        if (t > 0) {
            mbar_wait_parity(mbar_u32 + buf * 8, par[buf]);
            par[buf] ^= 1u;
        }

        // ---- dot: broadcast h, register W ----
        ull a00 = 0, a01 = 0, a02 = 0, a03 = 0;
        ull a10 = 0, a11 = 0, a12 = 0, a13 = 0;
        const float4* hrow = (const float4*)(hb + buf * 1024) + (wid << 4);
#pragma unroll
        for (int i = 0; i < 16; i++) {
            float4 h4 = hrow[i];
            ull p0 = pack2(h4.x), p1 = pack2(h4.y);
            ull p2 = pack2(h4.z), p3 = pack2(h4.w);
            ffma2(a00, p0, Wr0[i]); ffma2(a01, p1, Wr0[i]);
            ffma2(a02, p2, Wr0[i]); ffma2(a03, p3, Wr0[i]);
            ffma2(a10, p0, Wr1[i]); ffma2(a11, p1, Wr1[i]);
            ffma2(a12, p2, Wr1[i]); ffma2(a13, p3, Wr1[i]);
        }
        {
            ull* pb = part + (size_t)wid * 256 + lane;   // [wid][g][b][32]
            pb[0]   = a00; pb[32]  = a01; pb[64]  = a02; pb[96]  = a03;
            pb[128] = a10; pb[160] = a11; pb[192] = a12; pb[224] = a13;
        }
        __syncthreads();

        // ---- finalize (warps 0-3) ----
        if (tid < 128) {
            ull s0 = 0, s1 = 0;
            const ull* q = part + fb * 32 + vp;
#pragma unroll
            for (int w = 0; w < 16; w++) {
                s0 = add2(s0, q[w * 256]);
                s1 = add2(s1, q[w * 256 + 128]);
            }
            const float2 pj = unpack2(s0);
            const float2 pk = unpack2(s1);
            const float2 bj = *(const float2*)(bhs + 2 * vp);
            const float2 bk = *(const float2*)(bhs + 64 + 2 * vp);
            const float j0 = sigmoidf_fast(xj.x + pj.x + bj.x);
            const float j1 = sigmoidf_fast(xj.y + pj.y + bj.y);
            const float k0 = sigmoidf_fast(xk.x + pk.x + bk.x);
            const float k1 = sigmoidf_fast(xk.y + pk.y + bk.y);
            const float hn0 = j0 * (1.0f - hold0) + (1.0f - k0) * hold0;
            const float hn1 = j1 * (1.0f - hold1) + (1.0f - k1) * hold1;
            hold0 = hn0; hold1 = hn1;

            *(float2*)hsp = make_float2(hn0, hn1);
            hsp += 32 * 256;
            xpp += 2 * 32 * 256;

            if (t + 1 < Tt) {
                const uint32_t laddr = hb_u32 +
                    (uint32_t)(nbuf * 1024 + (v0 + 2 * vp) * 4 + fb) * 4u;
                const uint32_t lmbar = mbar_u32 + nbuf * 8;
                const uint32_t r0 = __float_as_uint(hn0);
                const uint32_t r1 = __float_as_uint(hn1);
#pragma unroll
                for (int r = 0; r < 4; r++) {
                    uint32_t ra, rm;
                    asm("mapa.shared::cluster.u32 %0, %1, %2;" : "=r"(ra) : "r"(laddr), "r"(r));
                    asm("mapa.shared::cluster.u32 %0, %1, %2;" : "=r"(rm) : "r"(lmbar), "r"(r));
                    asm volatile(
                        "st.async.shared::cluster.mbarrier::complete_tx::bytes.b32 [%0], %1, [%2];"
                        :: "r"(ra), "r"(r0), "r"(rm) : "memory");
                    asm volatile(
                        "st.async.shared::cluster.mbarrier::complete_tx::bytes.b32 [%0], %1, [%2];"
                        :: "r"(ra + 16), "r"(r1), "r"(rm) : "memory");
                }
            }
        }
        // No trailing syncthreads: next step's partial stores are gated by
        // the mbarrier (which needs this CTA's finalize reads done first).
    }

    asm volatile("barrier.cluster.arrive.aligned;" ::: "memory");
    asm volatile("barrier.cluster.wait.aligned;" ::: "memory");
}

// ============================================================
// Kernel 3: oscillator roll-out + output write.
// ============================================================
__global__ __launch_bounds__(256) void osc_kernel(float* __restrict__ out)
{
    const int t = blockIdx.x, b = blockIdx.y, u = threadIdx.x;
    const size_t base = ((size_t)t * 32 + b) * 256 + u;
    constexpr size_t CS = (size_t)200 * 32 * 256;
    float phi   = g_HS[0 * CS + base];
    float omega = g_HS[1 * CS + base];
    float r     = g_HS[2 * CS + base];
    float mu    = g_HS[3 * CS + base];
    float* o = out + ((size_t)b * 2000 + (size_t)t * 10) * 256 + u;
#pragma unroll
    for (int s = 0; s < OSC; s++) {
        o[(size_t)s * 256] = r * cosf(phi);
        r = r + (mu - r * r) * r;
        phi = phi + omega;
    }
}

// ============================================================
extern "C" void kernel_launch(void* const* d_in, const int* in_sizes, int n_in,
                              void* d_out, int out_size)
{
    const float* x  = (const float*)d_in[0];
    const float* Wx = (const float*)d_in[1];
    const float* bx = (const float*)d_in[2];
    const float* Wh = (const float*)d_in[3];
    const float* bh = (const float*)d_in[4];
    float* out = (float*)d_out;

    cudaFuncSetAttribute(rec_kernel, cudaFuncAttributeMaxDynamicSharedMemorySize,
                         REC_SMEM_BYTES);

    xp_gemm_kernel<<<dim3(2, 50, 8), 256>>>(x, Wx, bx);
    rec_kernel<<<dim3(4, 8, 4), 512, REC_SMEM_BYTES>>>(Wh, bh);
    osc_kernel<<<dim3(200, 32), 256>>>(out);
}